// round 8
// baseline (speedup 1.0000x reference)
#include <cuda_runtime.h>

// Detection1D: B=64, N=131072, C=1. Decode + per-batch greedy NMS (TOP_K=10).
// SINGLE fused kernel, "last block per batch does NMS" pattern.
//
//  Phase 1 (all 8192 blocks, 128 per batch): stream clf as float4, keep
//    scores > 0.999 (10th order statistic of 131072 uniforms ~0.99992 ->
//    provable superset of any greedy selection unless the shortlist
//    exhausts, which the fallback covers). Block-aggregated compaction:
//    one global atomicAdd per block into g_cnt[b]; write (score,idx).
//  Ticket: __threadfence (release) + atomicAdd(g_done[b]). Block seeing 127
//    is the last for its batch -> acquire fence -> runs NMS for that batch,
//    overlapped with other batches' filtering, same launch.
//  Phase 2 (64 last-blocks): gather+decode shortlist (~131 entries) into
//    smem with 256 threads, then warp 0 runs the 10 exact argmax+suppress
//    rounds (jnp.argmax tie-break via (score<<32)|~idx keys, __syncwarp
//    only). Shortlist overflow/exhaustion -> exact full-N fallback
//    (block-uniform branch, so its __syncthreads are safe). Resets
//    g_cnt/g_done at the end (static zero-init + self-reset = replay-safe).

#define NB 64
#define NN 131072          // 2^17
#define CAP 512
#define TOPK 10
#define THRESH 0.999f
#define BLKS_PER_B 128     // 131072 / 1024 elements per block

__device__ float2 g_cand[NB * CAP];   // (score, idx-as-float-bits)
__device__ int    g_cnt[NB];          // static zero-init; reset by last block
__device__ int    g_done[NB];         // ticket counters; reset by last block

__global__ void __launch_bounds__(256) k_fused(
    const float4* __restrict__ clf4,
    const float*  __restrict__ clf,
    const float2* __restrict__ reg,
    const float2* __restrict__ prop,
    float*        __restrict__ out)
{
    const int tid = threadIdx.x;
    const int b   = blockIdx.x >> 7;                 // batch of this block

    __shared__ int s_cnt, s_base, s_last;

    // ---------------- phase 1: filter this block's 1024 elements ------------
    if (tid == 0) s_cnt = 0;
    __syncthreads();

    {
        const int t  = blockIdx.x * 256 + tid;              // float4 index
        const unsigned e0 = ((unsigned)t * 4u) & (NN - 1u); // within-batch idx
        float4 s4 = clf4[t];
        float ss[4] = { s4.x, s4.y, s4.z, s4.w };

        float    csc[4];
        unsigned cid[4];
        int k = 0;
#pragma unroll
        for (int j = 0; j < 4; j++)
            if (ss[j] > THRESH) { csc[k] = ss[j]; cid[k] = e0 + j; k++; }

        int pos = 0;
        if (k) pos = atomicAdd(&s_cnt, k);                  // smem atomic
        __syncthreads();
        if (tid == 0)
            s_base = (s_cnt > 0) ? atomicAdd(&g_cnt[b], s_cnt) : 0;
        __syncthreads();

        const int base = s_base;
#pragma unroll
        for (int i = 0; i < 4; i++) {
            if (i < k) {
                int p = base + pos + i;
                if (p < CAP)
                    g_cand[b * CAP + p] =
                        make_float2(csc[i], __uint_as_float(cid[i]));
            }
        }
    }

    // ---------------- ticket: last block of this batch proceeds -------------
    __threadfence();          // release: make this thread's g_cand/g_cnt visible
    __syncthreads();
    if (tid == 0) {
        int v = atomicAdd(&g_done[b], 1);
        s_last = (v == BLKS_PER_B - 1);
    }
    __syncthreads();
    if (!s_last) return;      // block-uniform
    __threadfence();          // acquire: see all other blocks' writes

    // ---------------- phase 2: NMS for batch b ------------------------------
    __shared__ unsigned long long skey[CAP];
    __shared__ float sx1[CAP], sx2[CAP];
    __shared__ float selX1[TOPK], selX2[TOPK], selSc[TOPK];
    __shared__ unsigned selIdx[TOPK];
    __shared__ int s_nsel;
    __shared__ int s_mode;    // 0 = fast path, 1 = fallback needed, 2 = done

    const int cnt = g_cnt[b];
    const int m   = min(max(cnt, 0), CAP);
    if (tid == 0) { s_nsel = 0; s_mode = (cnt > CAP) ? 1 : 0; }

    const float2* regb  = reg  + (size_t)b * NN;
    const float2* propb = prop + (size_t)b * NN;

    // gather + decode shortlist (~131 entries), all 256 threads
    for (int i = tid; i < m; i += 256) {
        float2 c = g_cand[b * CAP + i];
        unsigned idx = __float_as_uint(c.y);
        float2 r = regb[idx];
        float2 p = propb[idx];
        float w   = p.y - p.x;
        float ctr = p.x + 0.5f * w;
        float pc  = ctr + (r.x * 0.1f) * w;
        float pw  = expf(r.y * 0.2f) * w;
        float x1 = fminf(fmaxf(pc - 0.5f * pw, 0.0f), 416.0f);
        float x2 = fminf(fmaxf(pc + 0.5f * pw, 0.0f), 416.0f);
        unsigned long long key = 0ULL;
        if (x2 - x1 > 3.0f)
            key = ((unsigned long long)__float_as_uint(c.x) << 32)
                | (unsigned long long)(0xFFFFFFFFu - idx);
        skey[i] = key;
        sx1[i]  = x1;
        sx2[i]  = x2;
    }
    __syncthreads();

    // ---------- fast path: warp 0 runs all TOPK rounds, no block barriers ---
    if (tid < 32 && s_mode == 0) {
        const int lane = tid;
        int nsel = 0;
        for (int t = 0; t < TOPK; t++) {
            unsigned long long best = 0ULL;
            float bx1 = 0.f, bx2 = 0.f;
            for (int i = lane; i < m; i += 32) {
                unsigned long long k = skey[i];
                if (k > best) { best = k; bx1 = sx1[i]; bx2 = sx2[i]; }
            }
#pragma unroll
            for (int o = 16; o > 0; o >>= 1) {
                unsigned long long k2 = __shfl_down_sync(0xFFFFFFFFu, best, o);
                float a2 = __shfl_down_sync(0xFFFFFFFFu, bx1, o);
                float b2 = __shfl_down_sync(0xFFFFFFFFu, bx2, o);
                if (k2 > best) { best = k2; bx1 = a2; bx2 = b2; }
            }
            best = __shfl_sync(0xFFFFFFFFu, best, 0);
            bx1  = __shfl_sync(0xFFFFFFFFu, bx1, 0);
            bx2  = __shfl_sync(0xFFFFFFFFu, bx2, 0);
            if (best == 0ULL) break;             // exhausted (warp-uniform)

            unsigned bidx = 0xFFFFFFFFu - (unsigned)(best & 0xFFFFFFFFu);
            if (lane == 0) {
                selSc[t]  = __uint_as_float((unsigned)(best >> 32));
                selIdx[t] = bidx;
                selX1[t]  = bx1;
                selX2[t]  = bx2;
            }
            nsel = t + 1;

            float blen = bx2 - bx1;
            for (int i = lane; i < m; i += 32) {
                unsigned long long k = skey[i];
                if (k == 0ULL) continue;
                float x1 = sx1[i], x2 = sx2[i];
                float inter = fmaxf(fminf(x2, bx2) - fmaxf(x1, bx1), 0.0f);
                float uni   = (x2 - x1) + blen - inter + 1e-9f;
                unsigned idx = 0xFFFFFFFFu - (unsigned)(k & 0xFFFFFFFFu);
                if (inter / uni > 0.5f || idx == bidx) skey[i] = 0ULL;
            }
            __syncwarp();
        }
        if (lane == 0) {
            s_nsel = nsel;
            if (nsel < TOPK) s_mode = 1;         // exhausted -> full-N fallback
        }
    }
    __syncthreads();

    // ---------- fallback: exact full-N scans (rarely/never runs) ------------
    if (s_mode == 1) {
        __shared__ unsigned long long r_key[8];
        __shared__ float r_x1[8], r_x2[8];
        const float* clfb = clf + (size_t)b * NN;
        for (int t = s_nsel; t < TOPK; t++) {
            unsigned long long best = 0ULL;
            float bx1 = 0.f, bx2 = 0.f;
            for (int i = tid; i < NN; i += 256) {
                float s = clfb[i];
                if (s <= 0.01f) continue;
                float2 r = regb[i];
                float2 p = propb[i];
                float w   = p.y - p.x;
                float ctr = p.x + 0.5f * w;
                float pc  = ctr + (r.x * 0.1f) * w;
                float pw  = expf(r.y * 0.2f) * w;
                float x1 = fminf(fmaxf(pc - 0.5f * pw, 0.0f), 416.0f);
                float x2 = fminf(fmaxf(pc + 0.5f * pw, 0.0f), 416.0f);
                float len = x2 - x1;
                if (len <= 3.0f) continue;
                bool sup = false;
                for (int j = 0; j < t; j++) {
                    if ((unsigned)i == selIdx[j]) { sup = true; break; }
                    float inter = fmaxf(fminf(x2, selX2[j]) - fmaxf(x1, selX1[j]), 0.0f);
                    float uni   = len + (selX2[j] - selX1[j]) - inter + 1e-9f;
                    if (inter / uni > 0.5f) { sup = true; break; }
                }
                if (sup) continue;
                unsigned long long k =
                    ((unsigned long long)__float_as_uint(s) << 32)
                  | (unsigned long long)(0xFFFFFFFFu - (unsigned)i);
                if (k > best) { best = k; bx1 = x1; bx2 = x2; }
            }
#pragma unroll
            for (int o = 16; o > 0; o >>= 1) {
                unsigned long long k2 = __shfl_down_sync(0xFFFFFFFFu, best, o);
                float a2 = __shfl_down_sync(0xFFFFFFFFu, bx1, o);
                float b2 = __shfl_down_sync(0xFFFFFFFFu, bx2, o);
                if (k2 > best) { best = k2; bx1 = a2; bx2 = b2; }
            }
            if ((tid & 31) == 0) {
                int w = tid >> 5;
                r_key[w] = best; r_x1[w] = bx1; r_x2[w] = bx2;
            }
            __syncthreads();
            if (tid == 0) {
                best = 0ULL;
#pragma unroll
                for (int w = 0; w < 8; w++)
                    if (r_key[w] > best) { best = r_key[w]; bx1 = r_x1[w]; bx2 = r_x2[w]; }
                if (best == 0ULL) {
                    s_mode = 2;   // nothing left -> -1 rows from here on
                } else {
                    selSc[t]  = __uint_as_float((unsigned)(best >> 32));
                    selIdx[t] = 0xFFFFFFFFu - (unsigned)(best & 0xFFFFFFFFu);
                    selX1[t]  = bx1;
                    selX2[t]  = bx2;
                    s_nsel = t + 1;
                }
            }
            __syncthreads();
            if (s_mode == 2) break;
        }
    }

    __syncthreads();
    if (tid < TOPK) {
        int t = tid;
        float a = -1.0f, c = -1.0f, s = -1.0f;
        if (t < s_nsel) { a = selX1[t]; c = selX2[t]; s = selSc[t]; }
        out[b * (TOPK * 3) + t * 3 + 0] = a;
        out[b * (TOPK * 3) + t * 3 + 1] = c;
        out[b * (TOPK * 3) + t * 3 + 2] = s;
    }
    if (tid == 0) {               // replay-clean state
        g_cnt[b]  = 0;
        g_done[b] = 0;
    }
}

extern "C" void kernel_launch(void* const* d_in, const int* in_sizes, int n_in,
                              void* d_out, int out_size)
{
    const float*  clf  = (const float*)d_in[0];                 // (64,131072,1)
    const float2* reg  = (const float2*)d_in[1];                // (64,131072,2)
    const float2* prop = (const float2*)d_in[2];                // (64,131072,2)
    float* out = (float*)d_out;                                 // (64,10,3)

    k_fused<<<NB * BLKS_PER_B, 256>>>((const float4*)clf, clf, reg, prop, out);
}

// round 9
// speedup vs baseline: 1.3581x; 1.3581x over previous
#include <cuda_runtime.h>

// Detection1D: B=64, N=131072, C=1. Decode + per-batch greedy NMS (TOP_K=10).
// ONE kernel, ONE block per batch, zero global scratch.
//
//  Phase 1: 1024 threads stream the batch's clf slice (32 float4 each,
//    coalesced). Scores > 0.999 (10th order statistic of 131072 uniforms
//    ~0.99992 -> provable superset of any greedy selection unless the
//    shortlist exhausts, which the fallback covers) push packed keys
//    (score_bits<<32)|~idx into SMEM via a smem atomic counter.
//  Phase 2: decode the ~131-entry shortlist (scattered reg/prop loads),
//    apply the length>3 test (key:=0 if short).
//  Phase 3: warp 0 runs the 10 exact argmax+suppress rounds entirely in
//    SMEM/registers (jnp.argmax tie-break via the packed keys; __syncwarp
//    only). Overflow/exhaustion -> exact full-N fallback (block-uniform,
//    so its __syncthreads are safe).

#define NB 64
#define NN 131072          // 2^17
#define NN4 (NN / 4)       // 32768 float4 per batch
#define NT 1024
#define CAP 512
#define TOPK 10
#define THRESH 0.999f

__global__ void __launch_bounds__(NT) k_all(
    const float4* __restrict__ clf4,
    const float*  __restrict__ clf,
    const float2* __restrict__ reg,
    const float2* __restrict__ prop,
    float*        __restrict__ out)
{
    const int b   = blockIdx.x;
    const int tid = threadIdx.x;

    __shared__ unsigned long long skey[CAP];
    __shared__ float sx1[CAP], sx2[CAP];
    __shared__ float selX1[TOPK], selX2[TOPK], selSc[TOPK];
    __shared__ unsigned selIdx[TOPK];
    __shared__ int s_cnt, s_nsel, s_mode;  // mode: 0 fast, 1 fallback, 2 done

    if (tid == 0) { s_cnt = 0; s_nsel = 0; s_mode = 0; }
    __syncthreads();

    // ---------------- phase 1: filter straight into SMEM --------------------
    {
        const float4* c4 = clf4 + (size_t)b * NN4;
#pragma unroll 4
        for (int i = tid; i < NN4; i += NT) {
            float4 s4 = c4[i];
            float ss[4] = { s4.x, s4.y, s4.z, s4.w };
#pragma unroll
            for (int j = 0; j < 4; j++) {
                if (ss[j] > THRESH) {
                    unsigned idx = (unsigned)(i * 4 + j);
                    int pos = atomicAdd(&s_cnt, 1);     // smem atomic, ~131 total
                    if (pos < CAP)
                        skey[pos] =
                            ((unsigned long long)__float_as_uint(ss[j]) << 32)
                          | (unsigned long long)(0xFFFFFFFFu - idx);
                }
            }
        }
    }
    __syncthreads();

    const int cnt = s_cnt;
    const int m   = min(cnt, CAP);
    if (tid == 0 && cnt > CAP) s_mode = 1;

    const float2* regb  = reg  + (size_t)b * NN;
    const float2* propb = prop + (size_t)b * NN;

    // ---------------- phase 2: decode shortlist -----------------------------
    for (int i = tid; i < m; i += NT) {
        unsigned long long key = skey[i];
        unsigned idx = 0xFFFFFFFFu - (unsigned)(key & 0xFFFFFFFFu);
        float2 r = regb[idx];
        float2 p = propb[idx];
        float w   = p.y - p.x;
        float ctr = p.x + 0.5f * w;
        float pc  = ctr + (r.x * 0.1f) * w;
        float pw  = expf(r.y * 0.2f) * w;
        float x1 = fminf(fmaxf(pc - 0.5f * pw, 0.0f), 416.0f);
        float x2 = fminf(fmaxf(pc + 0.5f * pw, 0.0f), 416.0f);
        if (!(x2 - x1 > 3.0f)) skey[i] = 0ULL;   // fails length test
        sx1[i] = x1;
        sx2[i] = x2;
    }
    __syncthreads();

    // ---------------- phase 3: warp 0, 10 argmax+suppress rounds ------------
    if (tid < 32 && s_mode == 0) {
        const int lane = tid;
        int nsel = 0;
        for (int t = 0; t < TOPK; t++) {
            unsigned long long best = 0ULL;
            float bx1 = 0.f, bx2 = 0.f;
            for (int i = lane; i < m; i += 32) {
                unsigned long long k = skey[i];
                if (k > best) { best = k; bx1 = sx1[i]; bx2 = sx2[i]; }
            }
#pragma unroll
            for (int o = 16; o > 0; o >>= 1) {
                unsigned long long k2 = __shfl_down_sync(0xFFFFFFFFu, best, o);
                float a2 = __shfl_down_sync(0xFFFFFFFFu, bx1, o);
                float b2 = __shfl_down_sync(0xFFFFFFFFu, bx2, o);
                if (k2 > best) { best = k2; bx1 = a2; bx2 = b2; }
            }
            best = __shfl_sync(0xFFFFFFFFu, best, 0);
            bx1  = __shfl_sync(0xFFFFFFFFu, bx1, 0);
            bx2  = __shfl_sync(0xFFFFFFFFu, bx2, 0);
            if (best == 0ULL) break;              // exhausted (warp-uniform)

            unsigned bidx = 0xFFFFFFFFu - (unsigned)(best & 0xFFFFFFFFu);
            if (lane == 0) {
                selSc[t]  = __uint_as_float((unsigned)(best >> 32));
                selIdx[t] = bidx;
                selX1[t]  = bx1;
                selX2[t]  = bx2;
            }
            nsel = t + 1;

            float blen = bx2 - bx1;
            for (int i = lane; i < m; i += 32) {
                unsigned long long k = skey[i];
                if (k == 0ULL) continue;
                float x1 = sx1[i], x2 = sx2[i];
                float inter = fmaxf(fminf(x2, bx2) - fmaxf(x1, bx1), 0.0f);
                float uni   = (x2 - x1) + blen - inter + 1e-9f;
                unsigned idx = 0xFFFFFFFFu - (unsigned)(k & 0xFFFFFFFFu);
                if (inter / uni > 0.5f || idx == bidx) skey[i] = 0ULL;
            }
            __syncwarp();
        }
        if (lane == 0) {
            s_nsel = nsel;
            if (nsel < TOPK) s_mode = 1;          // exhausted -> full-N fallback
        }
    }
    __syncthreads();

    // ---------------- fallback: exact full-N scans (rarely/never runs) ------
    if (s_mode == 1) {
        __shared__ unsigned long long r_key[NT / 32];
        __shared__ float r_x1[NT / 32], r_x2[NT / 32];
        const float* clfb = clf + (size_t)b * NN;
        for (int t = s_nsel; t < TOPK; t++) {
            unsigned long long best = 0ULL;
            float bx1 = 0.f, bx2 = 0.f;
            for (int i = tid; i < NN; i += NT) {
                float s = clfb[i];
                if (s <= 0.01f) continue;
                float2 r = regb[i];
                float2 p = propb[i];
                float w   = p.y - p.x;
                float ctr = p.x + 0.5f * w;
                float pc  = ctr + (r.x * 0.1f) * w;
                float pw  = expf(r.y * 0.2f) * w;
                float x1 = fminf(fmaxf(pc - 0.5f * pw, 0.0f), 416.0f);
                float x2 = fminf(fmaxf(pc + 0.5f * pw, 0.0f), 416.0f);
                float len = x2 - x1;
                if (len <= 3.0f) continue;
                bool sup = false;
                for (int j = 0; j < t; j++) {
                    if ((unsigned)i == selIdx[j]) { sup = true; break; }
                    float inter = fmaxf(fminf(x2, selX2[j]) - fmaxf(x1, selX1[j]), 0.0f);
                    float uni   = len + (selX2[j] - selX1[j]) - inter + 1e-9f;
                    if (inter / uni > 0.5f) { sup = true; break; }
                }
                if (sup) continue;
                unsigned long long k =
                    ((unsigned long long)__float_as_uint(s) << 32)
                  | (unsigned long long)(0xFFFFFFFFu - (unsigned)i);
                if (k > best) { best = k; bx1 = x1; bx2 = x2; }
            }
#pragma unroll
            for (int o = 16; o > 0; o >>= 1) {
                unsigned long long k2 = __shfl_down_sync(0xFFFFFFFFu, best, o);
                float a2 = __shfl_down_sync(0xFFFFFFFFu, bx1, o);
                float b2 = __shfl_down_sync(0xFFFFFFFFu, bx2, o);
                if (k2 > best) { best = k2; bx1 = a2; bx2 = b2; }
            }
            if ((tid & 31) == 0) {
                int w = tid >> 5;
                r_key[w] = best; r_x1[w] = bx1; r_x2[w] = bx2;
            }
            __syncthreads();
            if (tid == 0) {
                best = 0ULL;
                for (int w = 0; w < NT / 32; w++)
                    if (r_key[w] > best) { best = r_key[w]; bx1 = r_x1[w]; bx2 = r_x2[w]; }
                if (best == 0ULL) {
                    s_mode = 2;   // nothing left -> -1 rows from here on
                } else {
                    selSc[t]  = __uint_as_float((unsigned)(best >> 32));
                    selIdx[t] = 0xFFFFFFFFu - (unsigned)(best & 0xFFFFFFFFu);
                    selX1[t]  = bx1;
                    selX2[t]  = bx2;
                    s_nsel = t + 1;
                }
            }
            __syncthreads();
            if (s_mode == 2) break;
        }
    }

    __syncthreads();
    if (tid < TOPK) {
        int t = tid;
        float a = -1.0f, c = -1.0f, s = -1.0f;
        if (t < s_nsel) { a = selX1[t]; c = selX2[t]; s = selSc[t]; }
        out[b * (TOPK * 3) + t * 3 + 0] = a;
        out[b * (TOPK * 3) + t * 3 + 1] = c;
        out[b * (TOPK * 3) + t * 3 + 2] = s;
    }
}

extern "C" void kernel_launch(void* const* d_in, const int* in_sizes, int n_in,
                              void* d_out, int out_size)
{
    const float*  clf  = (const float*)d_in[0];                 // (64,131072,1)
    const float2* reg  = (const float2*)d_in[1];                // (64,131072,2)
    const float2* prop = (const float2*)d_in[2];                // (64,131072,2)
    float* out = (float*)d_out;                                 // (64,10,3)

    k_all<<<NB, NT>>>((const float4*)clf, clf, reg, prop, out);
}

// round 10
// speedup vs baseline: 1.3644x; 1.0046x over previous
#include <cuda_runtime.h>

// Detection1D: B=64, N=131072, C=1. Decode + per-batch greedy NMS (TOP_K=10).
// ONE kernel, ONE block per batch, zero global scratch.
//
//  Phase 1: 1024 threads stream the batch's clf slice. MLP-8: each
//    iteration front-batches 8 independent coalesced float4 loads into
//    registers (all in flight against DRAM latency), THEN tests. Scores
//    > 0.999 (10th order statistic of 131072 uniforms ~0.99992 -> provable
//    superset of any greedy selection unless the shortlist exhausts, which
//    the fallback covers) push packed keys (score_bits<<32)|~idx into SMEM
//    via a smem atomic counter (~131 pushes total).
//  Phase 2: decode the ~131-entry shortlist (scattered reg/prop loads),
//    apply the length>3 test (key:=0 if short).
//  Phase 3: warp 0 runs the 10 exact argmax+suppress rounds entirely in
//    SMEM/registers (jnp.argmax tie-break via the packed keys; __syncwarp
//    only). Overflow/exhaustion -> exact full-N fallback (block-uniform,
//    so its __syncthreads are safe).

#define NB 64
#define NN 131072          // 2^17
#define NN4 (NN / 4)       // 32768 float4 per batch
#define NT 1024
#define UF 8               // front-batched float4 loads per thread per iter
#define CAP 512
#define TOPK 10
#define THRESH 0.999f

__global__ void __launch_bounds__(NT) k_all(
    const float4* __restrict__ clf4,
    const float*  __restrict__ clf,
    const float2* __restrict__ reg,
    const float2* __restrict__ prop,
    float*        __restrict__ out)
{
    const int b   = blockIdx.x;
    const int tid = threadIdx.x;

    __shared__ unsigned long long skey[CAP];
    __shared__ float sx1[CAP], sx2[CAP];
    __shared__ float selX1[TOPK], selX2[TOPK], selSc[TOPK];
    __shared__ unsigned selIdx[TOPK];
    __shared__ int s_cnt, s_nsel, s_mode;  // mode: 0 fast, 1 fallback, 2 done

    if (tid == 0) { s_cnt = 0; s_nsel = 0; s_mode = 0; }
    __syncthreads();

    // ------------- phase 1: MLP-8 filter straight into SMEM -----------------
    {
        const float4* c4 = clf4 + (size_t)b * NN4;
        // NN4 = 4 * NT * UF exactly (32768 = 4*1024*8)
        for (int base = 0; base < NN4; base += NT * UF) {
            float4 v[UF];
#pragma unroll
            for (int u = 0; u < UF; u++)          // 8 independent coalesced loads
                v[u] = c4[base + u * NT + tid];
#pragma unroll
            for (int u = 0; u < UF; u++) {
                float ss[4] = { v[u].x, v[u].y, v[u].z, v[u].w };
                const unsigned e0 = (unsigned)((base + u * NT + tid) * 4);
#pragma unroll
                for (int j = 0; j < 4; j++) {
                    if (ss[j] > THRESH) {
                        int pos = atomicAdd(&s_cnt, 1);   // smem atomic, ~131 total
                        if (pos < CAP)
                            skey[pos] =
                                ((unsigned long long)__float_as_uint(ss[j]) << 32)
                              | (unsigned long long)(0xFFFFFFFFu - (e0 + j));
                    }
                }
            }
        }
    }
    __syncthreads();

    const int cnt = s_cnt;
    const int m   = min(cnt, CAP);
    if (tid == 0 && cnt > CAP) s_mode = 1;

    const float2* regb  = reg  + (size_t)b * NN;
    const float2* propb = prop + (size_t)b * NN;

    // ---------------- phase 2: decode shortlist -----------------------------
    for (int i = tid; i < m; i += NT) {
        unsigned long long key = skey[i];
        unsigned idx = 0xFFFFFFFFu - (unsigned)(key & 0xFFFFFFFFu);
        float2 r = regb[idx];
        float2 p = propb[idx];
        float w   = p.y - p.x;
        float ctr = p.x + 0.5f * w;
        float pc  = ctr + (r.x * 0.1f) * w;
        float pw  = expf(r.y * 0.2f) * w;
        float x1 = fminf(fmaxf(pc - 0.5f * pw, 0.0f), 416.0f);
        float x2 = fminf(fmaxf(pc + 0.5f * pw, 0.0f), 416.0f);
        if (!(x2 - x1 > 3.0f)) skey[i] = 0ULL;   // fails length test
        sx1[i] = x1;
        sx2[i] = x2;
    }
    __syncthreads();

    // ---------------- phase 3: warp 0, 10 argmax+suppress rounds ------------
    if (tid < 32 && s_mode == 0) {
        const int lane = tid;
        int nsel = 0;
        for (int t = 0; t < TOPK; t++) {
            unsigned long long best = 0ULL;
            float bx1 = 0.f, bx2 = 0.f;
            for (int i = lane; i < m; i += 32) {
                unsigned long long k = skey[i];
                if (k > best) { best = k; bx1 = sx1[i]; bx2 = sx2[i]; }
            }
#pragma unroll
            for (int o = 16; o > 0; o >>= 1) {
                unsigned long long k2 = __shfl_down_sync(0xFFFFFFFFu, best, o);
                float a2 = __shfl_down_sync(0xFFFFFFFFu, bx1, o);
                float b2 = __shfl_down_sync(0xFFFFFFFFu, bx2, o);
                if (k2 > best) { best = k2; bx1 = a2; bx2 = b2; }
            }
            best = __shfl_sync(0xFFFFFFFFu, best, 0);
            bx1  = __shfl_sync(0xFFFFFFFFu, bx1, 0);
            bx2  = __shfl_sync(0xFFFFFFFFu, bx2, 0);
            if (best == 0ULL) break;              // exhausted (warp-uniform)

            unsigned bidx = 0xFFFFFFFFu - (unsigned)(best & 0xFFFFFFFFu);
            if (lane == 0) {
                selSc[t]  = __uint_as_float((unsigned)(best >> 32));
                selIdx[t] = bidx;
                selX1[t]  = bx1;
                selX2[t]  = bx2;
            }
            nsel = t + 1;

            float blen = bx2 - bx1;
            for (int i = lane; i < m; i += 32) {
                unsigned long long k = skey[i];
                if (k == 0ULL) continue;
                float x1 = sx1[i], x2 = sx2[i];
                float inter = fmaxf(fminf(x2, bx2) - fmaxf(x1, bx1), 0.0f);
                float uni   = (x2 - x1) + blen - inter + 1e-9f;
                unsigned idx = 0xFFFFFFFFu - (unsigned)(k & 0xFFFFFFFFu);
                if (inter / uni > 0.5f || idx == bidx) skey[i] = 0ULL;
            }
            __syncwarp();
        }
        if (lane == 0) {
            s_nsel = nsel;
            if (nsel < TOPK) s_mode = 1;          // exhausted -> full-N fallback
        }
    }
    __syncthreads();

    // ---------------- fallback: exact full-N scans (rarely/never runs) ------
    if (s_mode == 1) {
        __shared__ unsigned long long r_key[NT / 32];
        __shared__ float r_x1[NT / 32], r_x2[NT / 32];
        const float* clfb = clf + (size_t)b * NN;
        for (int t = s_nsel; t < TOPK; t++) {
            unsigned long long best = 0ULL;
            float bx1 = 0.f, bx2 = 0.f;
            for (int i = tid; i < NN; i += NT) {
                float s = clfb[i];
                if (s <= 0.01f) continue;
                float2 r = regb[i];
                float2 p = propb[i];
                float w   = p.y - p.x;
                float ctr = p.x + 0.5f * w;
                float pc  = ctr + (r.x * 0.1f) * w;
                float pw  = expf(r.y * 0.2f) * w;
                float x1 = fminf(fmaxf(pc - 0.5f * pw, 0.0f), 416.0f);
                float x2 = fminf(fmaxf(pc + 0.5f * pw, 0.0f), 416.0f);
                float len = x2 - x1;
                if (len <= 3.0f) continue;
                bool sup = false;
                for (int j = 0; j < t; j++) {
                    if ((unsigned)i == selIdx[j]) { sup = true; break; }
                    float inter = fmaxf(fminf(x2, selX2[j]) - fmaxf(x1, selX1[j]), 0.0f);
                    float uni   = len + (selX2[j] - selX1[j]) - inter + 1e-9f;
                    if (inter / uni > 0.5f) { sup = true; break; }
                }
                if (sup) continue;
                unsigned long long k =
                    ((unsigned long long)__float_as_uint(s) << 32)
                  | (unsigned long long)(0xFFFFFFFFu - (unsigned)i);
                if (k > best) { best = k; bx1 = x1; bx2 = x2; }
            }
#pragma unroll
            for (int o = 16; o > 0; o >>= 1) {
                unsigned long long k2 = __shfl_down_sync(0xFFFFFFFFu, best, o);
                float a2 = __shfl_down_sync(0xFFFFFFFFu, bx1, o);
                float b2 = __shfl_down_sync(0xFFFFFFFFu, bx2, o);
                if (k2 > best) { best = k2; bx1 = a2; bx2 = b2; }
            }
            if ((tid & 31) == 0) {
                int w = tid >> 5;
                r_key[w] = best; r_x1[w] = bx1; r_x2[w] = bx2;
            }
            __syncthreads();
            if (tid == 0) {
                best = 0ULL;
                for (int w = 0; w < NT / 32; w++)
                    if (r_key[w] > best) { best = r_key[w]; bx1 = r_x1[w]; bx2 = r_x2[w]; }
                if (best == 0ULL) {
                    s_mode = 2;   // nothing left -> -1 rows from here on
                } else {
                    selSc[t]  = __uint_as_float((unsigned)(best >> 32));
                    selIdx[t] = 0xFFFFFFFFu - (unsigned)(best & 0xFFFFFFFFu);
                    selX1[t]  = bx1;
                    selX2[t]  = bx2;
                    s_nsel = t + 1;
                }
            }
            __syncthreads();
            if (s_mode == 2) break;
        }
    }

    __syncthreads();
    if (tid < TOPK) {
        int t = tid;
        float a = -1.0f, c = -1.0f, s = -1.0f;
        if (t < s_nsel) { a = selX1[t]; c = selX2[t]; s = selSc[t]; }
        out[b * (TOPK * 3) + t * 3 + 0] = a;
        out[b * (TOPK * 3) + t * 3 + 1] = c;
        out[b * (TOPK * 3) + t * 3 + 2] = s;
    }
}

extern "C" void kernel_launch(void* const* d_in, const int* in_sizes, int n_in,
                              void* d_out, int out_size)
{
    const float*  clf  = (const float*)d_in[0];                 // (64,131072,1)
    const float2* reg  = (const float2*)d_in[1];                // (64,131072,2)
    const float2* prop = (const float2*)d_in[2];                // (64,131072,2)
    float* out = (float*)d_out;                                 // (64,10,3)

    k_all<<<NB, NT>>>((const float4*)clf, clf, reg, prop, out);
}